// round 13
// baseline (speedup 1.0000x reference)
#include <cuda_runtime.h>
#include <cuda_bf16.h>
#include <cstdint>

#define N_ROIS 250000
#define G      128
#define NTOT   (N_ROIS + G)      // 250128 (< 2^18)
#define NBK    4096
#define CAP    320
#define TB     512
#define GRID_IOU 444             // 3 blocks per SM on 148 SMs
#define CHUNK  564               // ceil(NTOT / 444)

// ---------------- scratch (device globals; no allocation) ----------------
__device__ unsigned            g_bcnt[2][NBK];
__device__ unsigned long long  g_bucket[2][NBK * CAP];   // ~21 MB
__device__ unsigned            g_done;
__device__ unsigned            g_fin;
// all reset in-kernel for next replay; zero-init covers call #1.

// ---------------- threefry2x32 with key (0, 42) ----------------
__device__ __forceinline__ uint2 threefry42(unsigned x0, unsigned x1) {
    const unsigned ks0 = 0u;
    const unsigned ks1 = 42u;
    const unsigned ks2 = 0x1BD11BDAu ^ ks0 ^ ks1;
#define TF_ROUND(r) { x0 += x1; x1 = (x1 << (r)) | (x1 >> (32 - (r))); x1 ^= x0; }
    x0 += ks0; x1 += ks1;
    TF_ROUND(13) TF_ROUND(15) TF_ROUND(26) TF_ROUND(6)
    x0 += ks1; x1 += ks2 + 1u;
    TF_ROUND(17) TF_ROUND(29) TF_ROUND(16) TF_ROUND(24)
    x0 += ks2; x1 += ks0 + 2u;
    TF_ROUND(13) TF_ROUND(15) TF_ROUND(26) TF_ROUND(6)
    x0 += ks0; x1 += ks1 + 3u;
    TF_ROUND(17) TF_ROUND(29) TF_ROUND(16) TF_ROUND(24)
    x0 += ks1; x1 += ks2 + 4u;
    TF_ROUND(13) TF_ROUND(15) TF_ROUND(26) TF_ROUND(6)
    x0 += ks2; x1 += ks0 + 5u;
#undef TF_ROUND
    return make_uint2(x0, x1);
}

// load roi i's box (i < NTOT)
__device__ __forceinline__ void load_box(const float* __restrict__ rois,
                                         const float* __restrict__ gtb, int ii,
                                         float& x1, float& y1, float& x2, float& y2) {
    if (ii < N_ROIS) {
        const float* p = rois + (size_t)ii * 5;
        x1 = p[1]; y1 = p[2]; x2 = p[3]; y2 = p[4];
    } else {
        const float* p = gtb + (size_t)(ii - N_ROIS) * 4;
        x1 = p[0]; y1 = p[1]; x2 = p[2]; y2 = p[3];
    }
}

// emit candidate record for roi i given best (bn, bs, bj)
__device__ __forceinline__ void emit(int i, float bn, float bs, int bj) {
    float mov = __fdiv_rn(bn, bs - bn);   // reference max-overlap value
    bool fg = (mov >= 0.5f);
    bool bg = (mov < 0.5f) && (mov >= 0.1f);
    if (fg || bg) {
        uint2 y = threefry42(0u, (unsigned)i);
        unsigned m = ((y.x ^ y.y) >> 9) + 1u;   // 1 .. 2^23, monotone in u
        unsigned long long rec =
            ((unsigned long long)m << 25) |
            ((unsigned long long)(0x3FFFFu - (unsigned)i) << 7) |
            (unsigned long long)(unsigned)bj;
        int sel = fg ? 0 : 1;
        unsigned bb = (m - 1u) >> 11;                 // 0..4095
        unsigned p = atomicAdd(&g_bcnt[sel][bb], 1u);
        if (p < CAP) g_bucket[sel][(size_t)bb * CAP + p] = rec;
    }
}

// one roi's full IoU argmax scan over shared gt boxes
__device__ __forceinline__ void iou_scan(const float4* sb, const float* sa,
                                         float ax1, float ay1, float ax2, float ay2,
                                         float& bn, float& bs, int& bj) {
    float aa = __fmul_rn(ax2 - ax1 + 1.0f, ay2 - ay1 + 1.0f);
    bn = 0.0f; bs = 1.0f; bj = 0;
#pragma unroll 4
    for (int j = 0; j < G; j++) {
        float4 b = sb[j];
        float xx1 = fmaxf(ax1, b.x);
        float yy1 = fmaxf(ay1, b.y);
        float xx2 = fminf(ax2, b.z);
        float yy2 = fminf(ay2, b.w);
        float iw = fmaxf(xx2 - xx1 + 1.0f, 0.0f);
        float ih = fmaxf(yy2 - yy1 + 1.0f, 0.0f);
        float inter = __fmul_rn(iw, ih);
        float S = aa + sa[j];   // reference rounding
        // ordering of inter/(S-inter) == ordering of inter/S (exact, S>0)
        if (__fmul_rn(inter, bs) > __fmul_rn(bn, S)) {
            bn = inter; bs = S; bj = j;
        }
    }
}

// ---------------- select path (noinline keeps hot-loop regs clean) ----------------
__device__ __noinline__ void do_select(int sel,
                                       const float* __restrict__ rois,
                                       const float* __restrict__ gtb,
                                       const int* __restrict__ gtl,
                                       float* __restrict__ out) {
    __shared__ unsigned           swsum[16];
    __shared__ int                sB;
    __shared__ unsigned           sM;
    __shared__ unsigned short     s_ebin[512];
    __shared__ unsigned short     s_eoff[512];
    __shared__ unsigned long long skey[512];
    __shared__ int                s_lab[128];
    __shared__ float              s_tgt[128][4];

    int t = threadIdx.x;
    int lane = t & 31, w = t >> 5;

    if (t == 0) { sB = 0; sM = 0u; }

    // 8 bins per thread
    unsigned loc[8];
    unsigned csum = 0;
#pragma unroll
    for (int k = 0; k < 8; k++) { loc[k] = g_bcnt[sel][t * 8 + k]; csum += loc[k]; }

    // warp suffix scan (inclusive from high lane)
    unsigned s = csum;
#pragma unroll
    for (int d = 1; d < 32; d <<= 1) {
        unsigned v = __shfl_down_sync(0xFFFFFFFFu, s, d);
        if (lane + d < 32) s += v;
    }
    if (lane == 0) swsum[w] = s;
    __syncthreads();

    unsigned wex = 0;
    for (int w2 = w + 1; w2 < 16; w2++) wex += swsum[w2];
    unsigned ex = wex + (s - csum);   // entries in bins strictly above my chunk

    unsigned Carr[8];
    {
        unsigned suf = 0;
#pragma unroll
        for (int k = 7; k >= 0; k--) { suf += loc[k]; Carr[k] = ex + suf; }
    }

    // unique boundary bin: C(b) >= 128 and C(b)-cnt(b) < 128 -> single writer
#pragma unroll
    for (int k = 0; k < 8; k++) {
        unsigned C = Carr[k];
        if (C >= 128u && (C - loc[k]) < 128u) { sB = t * 8 + k; sM = C; }
    }
    if (t == 0 && Carr[0] < 128u) sM = Carr[0];   // degenerate: < 128 total
    __syncthreads();
    int B = sB;
    unsigned M = sM; if (M > 512u) M = 512u;

    // position -> (bin, offset-within-bin) map; suffix scan makes positions disjoint
#pragma unroll
    for (int k = 0; k < 8; k++) {
        int bin = t * 8 + k;
        if (bin >= B && loc[k] > 0u) {
            unsigned cnt = loc[k] < CAP ? loc[k] : CAP;
            unsigned off = Carr[k] - loc[k];
            for (unsigned e2 = 0; e2 < cnt; e2++) {
                unsigned pos = off + e2;
                if (pos < 512u) { s_ebin[pos] = (unsigned short)bin; s_eoff[pos] = (unsigned short)e2; }
            }
        }
    }
    __syncthreads();

    // O(1) gather per entry (L2-hot: written moments ago)
    for (unsigned e = t; e < M; e += 512)
        skey[e] = g_bucket[sel][(size_t)s_ebin[e] * CAP + s_eoff[e]];
    __syncthreads();

    // rank by counting (keys unique via embedded ~idx); rank 0 = largest
    int rank = -1;
    unsigned long long mykey = 0ull;
    if (t < (int)M) {
        mykey = skey[t];
        int r = 0;
        for (unsigned j = 0; j < M; j++) r += (skey[j] > mykey) ? 1 : 0;
        rank = r;
    }

    // row writes by rank
    bool emitrow = (rank >= 0 && rank < 128);
    bool pad     = (rank < 0 && t < 128 && (unsigned)t >= M);   // degenerate only
    if (emitrow || pad) {
        int r = emitrow ? rank : t;
        unsigned long long rec = emitrow ? mykey : 0ull;
        unsigned idx = 0x3FFFFu - (unsigned)((rec >> 7) & 0x3FFFFu);
        int ga = (int)(rec & 0x7Fu);
        if (idx >= NTOT) { idx = 0; ga = 0; }

        float c0, x1, y1, x2, y2;
        if (idx < N_ROIS) {
            const float* p = rois + (size_t)idx * 5;
            c0 = p[0]; x1 = p[1]; y1 = p[2]; x2 = p[3]; y2 = p[4];
        } else {
            const float* p = gtb + (size_t)(idx - N_ROIS) * 4;
            c0 = 0.0f; x1 = p[0]; y1 = p[1]; x2 = p[2]; y2 = p[3];
        }

        int rg = sel * 128 + r;   // global row 0..255
        int label = (sel == 0) ? gtl[ga] : 0;  // valid_fg always true (gt self-match)
        s_lab[r] = label;

        out[rg * 5 + 0] = c0;
        out[rg * 5 + 1] = x1;
        out[rg * 5 + 2] = y1;
        out[rg * 5 + 3] = x2;
        out[rg * 5 + 4] = y2;
        out[1280 + rg] = (float)label;

        const float* g = gtb + (size_t)ga * 4;
        float ew = x2 - x1 + 1.0f, eh = y2 - y1 + 1.0f;
        float ecx = x1 + 0.5f * ew, ecy = y1 + 0.5f * eh;
        float gw = g[2] - g[0] + 1.0f, gh = g[3] - g[1] + 1.0f;
        float gcx = g[0] + 0.5f * gw, gcy = g[1] + 0.5f * gh;
        s_tgt[r][0] = (gcx - ecx) / ew;
        s_tgt[r][1] = (gcy - ecy) / eh;
        s_tgt[r][2] = logf(gw / ew);
        s_tgt[r][3] = logf(gh / eh);
    }
    __syncthreads();

    // bbox_targets slab (128 rows x 84), coalesced
    float* slab = out + 1536 + (size_t)sel * 128 * 84;
    for (int e = t; e < 128 * 84; e += 512) {
        int row = e / 84;
        int col = e - row * 84;
        int lab = s_lab[row];
        float v = 0.0f;
        int c0 = lab * 4;
        if (lab > 0 && col >= c0 && col < c0 + 4)
            v = s_tgt[row][col - c0];
        slab[e] = v;
    }

    // re-zero this selector's bucket counters for the next replay
#pragma unroll
    for (int k = 0; k < 8; k++) g_bcnt[sel][t * 8 + k] = 0u;
}

// ================= single kernel: 444 IoU blocks + 2 waiter/select blocks =================
__global__ void __launch_bounds__(TB, 3) k_all(const float* __restrict__ rois,
                                               const float* __restrict__ gtb,
                                               const int* __restrict__ gtl,
                                               float* __restrict__ out) {
    int tid = threadIdx.x;

    if (blockIdx.x >= GRID_IOU) {
        // ---------- select block: wait for all IoU blocks, then select ----------
        int sel = blockIdx.x - GRID_IOU;
        if (tid == 0) {
            unsigned v;
            do {
                asm volatile("ld.volatile.global.u32 %0, [%1];" : "=r"(v) : "l"(&g_done));
            } while (v < (unsigned)GRID_IOU);
        }
        __syncthreads();
        __threadfence();   // acquire: order bucket reads after g_done observation
        do_select(sel, rois, gtb, gtl, out);

        // handshake reset (second finisher clears; both already passed the wait)
        __syncthreads();
        if (tid == 0) {
            unsigned old = atomicAdd(&g_fin, 1u);
            if (old == 1u) { g_done = 0u; g_fin = 0u; }
        }
        return;
    }

    // ---------- IoU block ----------
    __shared__ float4 sb[G];   // gt x1,y1,x2,y2
    __shared__ float  sa[G];   // gt area
    if (tid < G) {
        float x1 = gtb[tid * 4 + 0], y1 = gtb[tid * 4 + 1];
        float x2 = gtb[tid * 4 + 2], y2 = gtb[tid * 4 + 3];
        sb[tid] = make_float4(x1, y1, x2, y2);
        sa[tid] = __fmul_rn(x2 - x1 + 1.0f, y2 - y1 + 1.0f);
    }
    __syncthreads();

    int start = blockIdx.x * CHUNK;
    int count = NTOT - start; if (count > CHUNK) count = CHUNK;

    if (tid < count) {
        int i = start + tid;
        float ax1, ay1, ax2, ay2, bn, bs; int bj;
        load_box(rois, gtb, i, ax1, ay1, ax2, ay2);
        iou_scan(sb, sa, ax1, ay1, ax2, ay2, bn, bs, bj);
        emit(i, bn, bs, bj);
    }
    if (tid < count - TB) {
        int i = start + TB + tid;
        float ax1, ay1, ax2, ay2, bn, bs; int bj;
        load_box(rois, gtb, i, ax1, ay1, ax2, ay2);
        iou_scan(sb, sa, ax1, ay1, ax2, ay2, bn, bs, bj);
        emit(i, bn, bs, bj);
    }

    // publish: stores visible, then count this block done
    __threadfence();
    __syncthreads();
    if (tid == 0) atomicAdd(&g_done, 1u);
}

// ---------------- launch ----------------
extern "C" void kernel_launch(void* const* d_in, const int* in_sizes, int n_in,
                              void* d_out, int out_size) {
    const float* all_rois = nullptr;  // 1,250,000 elems
    const float* gtb      = nullptr;  // 512 elems
    const int*   gtl      = nullptr;  // 128 elems
    for (int k = 0; k < n_in; k++) {
        if (in_sizes[k] == N_ROIS * 5) all_rois = (const float*)d_in[k];
        else if (in_sizes[k] == G * 4) gtb = (const float*)d_in[k];
        else if (in_sizes[k] == G)     gtl = (const int*)d_in[k];
    }
    float* out = (float*)d_out;

    k_all<<<GRID_IOU + 2, TB>>>(all_rois, gtb, gtl, out);
}

// round 14
// speedup vs baseline: 1.0985x; 1.0985x over previous
#include <cuda_runtime.h>
#include <cuda_bf16.h>
#include <cstdint>

#define N_ROIS 250000
#define G      128
#define NTOT   (N_ROIS + G)      // 250128 (< 2^18)
#define NBK    4096
#define CAP    320
#define TB     512
#define GRID_IOU 296             // 2 blocks per SM on 148 SMs
#define CHUNK  846               // ceil(NTOT / 296); every block has count >= 512

// ---------------- scratch (device globals; no allocation) ----------------
__device__ unsigned            g_bcnt[2][NBK];
__device__ unsigned long long  g_bucket[2][NBK * CAP];   // ~21 MB
__device__ unsigned            g_done;
__device__ unsigned            g_fin;
// all reset in-kernel for next replay; zero-init covers call #1.

// ---------------- threefry2x32 with key (0, 42) ----------------
__device__ __forceinline__ uint2 threefry42(unsigned x0, unsigned x1) {
    const unsigned ks0 = 0u;
    const unsigned ks1 = 42u;
    const unsigned ks2 = 0x1BD11BDAu ^ ks0 ^ ks1;
#define TF_ROUND(r) { x0 += x1; x1 = (x1 << (r)) | (x1 >> (32 - (r))); x1 ^= x0; }
    x0 += ks0; x1 += ks1;
    TF_ROUND(13) TF_ROUND(15) TF_ROUND(26) TF_ROUND(6)
    x0 += ks1; x1 += ks2 + 1u;
    TF_ROUND(17) TF_ROUND(29) TF_ROUND(16) TF_ROUND(24)
    x0 += ks2; x1 += ks0 + 2u;
    TF_ROUND(13) TF_ROUND(15) TF_ROUND(26) TF_ROUND(6)
    x0 += ks0; x1 += ks1 + 3u;
    TF_ROUND(17) TF_ROUND(29) TF_ROUND(16) TF_ROUND(24)
    x0 += ks1; x1 += ks2 + 4u;
    TF_ROUND(13) TF_ROUND(15) TF_ROUND(26) TF_ROUND(6)
    x0 += ks2; x1 += ks0 + 5u;
#undef TF_ROUND
    return make_uint2(x0, x1);
}

// load roi i's box (i < NTOT)
__device__ __forceinline__ void load_box(const float* __restrict__ rois,
                                         const float* __restrict__ gtb, int ii,
                                         float& x1, float& y1, float& x2, float& y2) {
    if (ii < N_ROIS) {
        const float* p = rois + (size_t)ii * 5;
        x1 = p[1]; y1 = p[2]; x2 = p[3]; y2 = p[4];
    } else {
        const float* p = gtb + (size_t)(ii - N_ROIS) * 4;
        x1 = p[0]; y1 = p[1]; x2 = p[2]; y2 = p[3];
    }
}

// emit candidate record for roi i given best (bn, bs, bj)
__device__ __forceinline__ void emit(int i, float bn, float bs, int bj) {
    float mov = __fdiv_rn(bn, bs - bn);   // reference max-overlap value
    bool fg = (mov >= 0.5f);
    bool bg = (mov < 0.5f) && (mov >= 0.1f);
    if (fg || bg) {
        uint2 y = threefry42(0u, (unsigned)i);
        unsigned m = ((y.x ^ y.y) >> 9) + 1u;   // 1 .. 2^23, monotone in u
        unsigned long long rec =
            ((unsigned long long)m << 25) |
            ((unsigned long long)(0x3FFFFu - (unsigned)i) << 7) |
            (unsigned long long)(unsigned)bj;
        int sel = fg ? 0 : 1;
        unsigned bb = (m - 1u) >> 11;                 // 0..4095
        unsigned p = atomicAdd(&g_bcnt[sel][bb], 1u);
        if (p < CAP) g_bucket[sel][(size_t)bb * CAP + p] = rec;
    }
}

// one roi's full IoU argmax scan; sb holds (gx1, gy1, gx2+1, gy2+1), sa gt area.
// ax2p/ay2p are ax2+1/ay2+1; aa computed from raw coords (reference rounding).
__device__ __forceinline__ void iou_scan(const float4* sb, const float* sa,
                                         float ax1, float ay1, float ax2p, float ay2p,
                                         float aa, float& bn, float& bs, int& bj) {
    bn = 0.0f; bs = 1.0f; bj = 0;
#pragma unroll 4
    for (int j = 0; j < G; j++) {
        float4 b = sb[j];
        float xx1  = fmaxf(ax1, b.x);
        float yy1  = fmaxf(ay1, b.y);
        float xx2p = fminf(ax2p, b.z);
        float yy2p = fminf(ay2p, b.w);
        float iw = fmaxf(xx2p - xx1, 0.0f);   // == max((xx2+1)-xx1, 0); +1 hoisted thru min
        float ih = fmaxf(yy2p - yy1, 0.0f);
        float inter = __fmul_rn(iw, ih);
        float S = aa + sa[j];
        // ordering of inter/(S-inter) == ordering of inter/S (exact, S>0)
        if (__fmul_rn(inter, bs) > __fmul_rn(bn, S)) {
            bn = inter; bs = S; bj = j;
        }
    }
}

// ---------------- select path (noinline keeps hot-loop regs clean) ----------------
__device__ __noinline__ void do_select(int sel,
                                       const float* __restrict__ rois,
                                       const float* __restrict__ gtb,
                                       const int* __restrict__ gtl,
                                       float* __restrict__ out) {
    __shared__ unsigned           swsum[16];
    __shared__ int                sB;
    __shared__ unsigned           sM;
    __shared__ unsigned short     s_ebin[512];
    __shared__ unsigned short     s_eoff[512];
    __shared__ unsigned long long skey[512];
    __shared__ int                s_lab[128];
    __shared__ float              s_tgt[128][4];

    int t = threadIdx.x;
    int lane = t & 31, w = t >> 5;

    if (t == 0) { sB = 0; sM = 0u; }

    unsigned loc[8];
    unsigned csum = 0;
#pragma unroll
    for (int k = 0; k < 8; k++) { loc[k] = g_bcnt[sel][t * 8 + k]; csum += loc[k]; }

    // warp suffix scan (inclusive from high lane)
    unsigned s = csum;
#pragma unroll
    for (int d = 1; d < 32; d <<= 1) {
        unsigned v = __shfl_down_sync(0xFFFFFFFFu, s, d);
        if (lane + d < 32) s += v;
    }
    if (lane == 0) swsum[w] = s;
    __syncthreads();

    unsigned wex = 0;
    for (int w2 = w + 1; w2 < 16; w2++) wex += swsum[w2];
    unsigned ex = wex + (s - csum);   // entries in bins strictly above my chunk

    unsigned Carr[8];
    {
        unsigned suf = 0;
#pragma unroll
        for (int k = 7; k >= 0; k--) { suf += loc[k]; Carr[k] = ex + suf; }
    }

    // unique boundary bin: C(b) >= 128 and C(b)-cnt(b) < 128 -> single writer
#pragma unroll
    for (int k = 0; k < 8; k++) {
        unsigned C = Carr[k];
        if (C >= 128u && (C - loc[k]) < 128u) { sB = t * 8 + k; sM = C; }
    }
    if (t == 0 && Carr[0] < 128u) sM = Carr[0];   // degenerate: < 128 total
    __syncthreads();
    int B = sB;
    unsigned M = sM; if (M > 512u) M = 512u;

    // position -> (bin, offset-within-bin) map; suffix scan makes positions disjoint
#pragma unroll
    for (int k = 0; k < 8; k++) {
        int bin = t * 8 + k;
        if (bin >= B && loc[k] > 0u) {
            unsigned cnt = loc[k] < CAP ? loc[k] : CAP;
            unsigned off = Carr[k] - loc[k];
            for (unsigned e2 = 0; e2 < cnt; e2++) {
                unsigned pos = off + e2;
                if (pos < 512u) { s_ebin[pos] = (unsigned short)bin; s_eoff[pos] = (unsigned short)e2; }
            }
        }
    }
    __syncthreads();

    // O(1) gather per entry (L2-hot: written moments ago)
    for (unsigned e = t; e < M; e += 512)
        skey[e] = g_bucket[sel][(size_t)s_ebin[e] * CAP + s_eoff[e]];
    __syncthreads();

    // rank by counting (keys unique via embedded ~idx); rank 0 = largest
    int rank = -1;
    unsigned long long mykey = 0ull;
    if (t < (int)M) {
        mykey = skey[t];
        int r = 0;
        for (unsigned j = 0; j < M; j++) r += (skey[j] > mykey) ? 1 : 0;
        rank = r;
    }

    // row writes by rank
    bool emitrow = (rank >= 0 && rank < 128);
    bool pad     = (rank < 0 && t < 128 && (unsigned)t >= M);   // degenerate only
    if (emitrow || pad) {
        int r = emitrow ? rank : t;
        unsigned long long rec = emitrow ? mykey : 0ull;
        unsigned idx = 0x3FFFFu - (unsigned)((rec >> 7) & 0x3FFFFu);
        int ga = (int)(rec & 0x7Fu);
        if (idx >= NTOT) { idx = 0; ga = 0; }

        float c0, x1, y1, x2, y2;
        if (idx < N_ROIS) {
            const float* p = rois + (size_t)idx * 5;
            c0 = p[0]; x1 = p[1]; y1 = p[2]; x2 = p[3]; y2 = p[4];
        } else {
            const float* p = gtb + (size_t)(idx - N_ROIS) * 4;
            c0 = 0.0f; x1 = p[0]; y1 = p[1]; x2 = p[2]; y2 = p[3];
        }

        int rg = sel * 128 + r;   // global row 0..255
        int label = (sel == 0) ? gtl[ga] : 0;  // valid_fg always true (gt self-match)
        s_lab[r] = label;

        out[rg * 5 + 0] = c0;
        out[rg * 5 + 1] = x1;
        out[rg * 5 + 2] = y1;
        out[rg * 5 + 3] = x2;
        out[rg * 5 + 4] = y2;
        out[1280 + rg] = (float)label;

        const float* g = gtb + (size_t)ga * 4;
        float ew = x2 - x1 + 1.0f, eh = y2 - y1 + 1.0f;
        float ecx = x1 + 0.5f * ew, ecy = y1 + 0.5f * eh;
        float gw = g[2] - g[0] + 1.0f, gh = g[3] - g[1] + 1.0f;
        float gcx = g[0] + 0.5f * gw, gcy = g[1] + 0.5f * gh;
        s_tgt[r][0] = (gcx - ecx) / ew;
        s_tgt[r][1] = (gcy - ecy) / eh;
        s_tgt[r][2] = logf(gw / ew);
        s_tgt[r][3] = logf(gh / eh);
    }
    __syncthreads();

    // bbox_targets slab (128 rows x 84), coalesced
    float* slab = out + 1536 + (size_t)sel * 128 * 84;
    for (int e = t; e < 128 * 84; e += 512) {
        int row = e / 84;
        int col = e - row * 84;
        int lab = s_lab[row];
        float v = 0.0f;
        int c0 = lab * 4;
        if (lab > 0 && col >= c0 && col < c0 + 4)
            v = s_tgt[row][col - c0];
        slab[e] = v;
    }

    // re-zero this selector's bucket counters for the next replay
#pragma unroll
    for (int k = 0; k < 8; k++) g_bcnt[sel][t * 8 + k] = 0u;
}

// ================= single kernel: 296 IoU blocks + 2 waiter/select blocks =================
__global__ void __launch_bounds__(TB, 2) k_all(const float* __restrict__ rois,
                                               const float* __restrict__ gtb,
                                               const int* __restrict__ gtl,
                                               float* __restrict__ out) {
    int tid = threadIdx.x;

    if (blockIdx.x >= GRID_IOU) {
        // ---------- select block: wait for all IoU blocks, then select ----------
        int sel = blockIdx.x - GRID_IOU;
        if (tid == 0) {
            unsigned v;
            do {
                asm volatile("ld.volatile.global.u32 %0, [%1];" : "=r"(v) : "l"(&g_done));
            } while (v < (unsigned)GRID_IOU);
        }
        __syncthreads();
        __threadfence();   // acquire: order bucket reads after g_done observation
        do_select(sel, rois, gtb, gtl, out);

        // handshake reset (second finisher clears; both already passed the wait)
        __syncthreads();
        if (tid == 0) {
            unsigned old = atomicAdd(&g_fin, 1u);
            if (old == 1u) { g_done = 0u; g_fin = 0u; }
        }
        return;
    }

    // ---------- IoU block ----------
    __shared__ float4 sb[G];   // gt (x1, y1, x2+1, y2+1)
    __shared__ float  sa[G];   // gt area (raw-coord reference rounding)
    if (tid < G) {
        float x1 = gtb[tid * 4 + 0], y1 = gtb[tid * 4 + 1];
        float x2 = gtb[tid * 4 + 2], y2 = gtb[tid * 4 + 3];
        sa[tid] = __fmul_rn(x2 - x1 + 1.0f, y2 - y1 + 1.0f);
        sb[tid] = make_float4(x1, y1, x2 + 1.0f, y2 + 1.0f);
    }
    __syncthreads();

    int start = blockIdx.x * CHUNK;
    int count = NTOT - start; if (count > CHUNK) count = CHUNK;   // >= 512 always

    {
        int i = start + tid;
        float ax1, ay1, ax2, ay2, bn, bs; int bj;
        load_box(rois, gtb, i, ax1, ay1, ax2, ay2);
        float aa = __fmul_rn(ax2 - ax1 + 1.0f, ay2 - ay1 + 1.0f);  // raw coords first
        iou_scan(sb, sa, ax1, ay1, ax2 + 1.0f, ay2 + 1.0f, aa, bn, bs, bj);
        emit(i, bn, bs, bj);
    }
    if (tid < count - TB) {
        int i = start + TB + tid;
        float ax1, ay1, ax2, ay2, bn, bs; int bj;
        load_box(rois, gtb, i, ax1, ay1, ax2, ay2);
        float aa = __fmul_rn(ax2 - ax1 + 1.0f, ay2 - ay1 + 1.0f);
        iou_scan(sb, sa, ax1, ay1, ax2 + 1.0f, ay2 + 1.0f, aa, bn, bs, bj);
        emit(i, bn, bs, bj);
    }

    // publish: stores visible, then count this block done
    __threadfence();
    __syncthreads();
    if (tid == 0) atomicAdd(&g_done, 1u);
}

// ---------------- launch ----------------
extern "C" void kernel_launch(void* const* d_in, const int* in_sizes, int n_in,
                              void* d_out, int out_size) {
    const float* all_rois = nullptr;  // 1,250,000 elems
    const float* gtb      = nullptr;  // 512 elems
    const int*   gtl      = nullptr;  // 128 elems
    for (int k = 0; k < n_in; k++) {
        if (in_sizes[k] == N_ROIS * 5) all_rois = (const float*)d_in[k];
        else if (in_sizes[k] == G * 4) gtb = (const float*)d_in[k];
        else if (in_sizes[k] == G)     gtl = (const int*)d_in[k];
    }
    float* out = (float*)d_out;

    k_all<<<GRID_IOU + 2, TB>>>(all_rois, gtb, gtl, out);
}